// round 2
// baseline (speedup 1.0000x reference)
#include <cuda_runtime.h>
#include <cstdint>
#include <math_constants.h>

#define FULLMASK 0xFFFFFFFFu

static constexpr int N_ROWS = 262144;
static constexpr int D      = 256;
static constexpr int KCODES = 640;

static constexpr int BM = 128;     // rows per CTA tile
static constexpr int BK = 16;      // k-chunk
static constexpr int BN_PAD = 132; // padded code stride (floats), 16B-aligned rows
static constexpr int P3_BASE  = 385;
static constexpr int P3_CODES = 127;

#define MARGIN 1e-2f

__constant__ int c_starts[6] = {0, 129, 257, 385, 513, 577};
__constant__ int c_ends[6]   = {128, 256, 384, 512, 576, 640};

__device__ double g_loss_sum;
__device__ int    g_rare_cnt;
__device__ int    g_rare_idx[N_ROWS];
__device__ float  g_csum[KCODES];   // 0.5 * ||w_k||^2

// NOTE: x is int32 on device (JAX x64 disabled downcasts the reference's int64).
__device__ __forceinline__ int partition_id(int at) {
    if (at == 5)   return 0;
    if (at == 6)   return 1;
    if (at == 7)   return 2;
    if (at == 119) return 4;
    if (at == 120) return 5;
    return 3;
}

__device__ __forceinline__ unsigned long long dup_f32(float v) {
    unsigned long long r;
    unsigned int u = __float_as_uint(v);
    asm("mov.b64 %0, {%1, %1};" : "=l"(r) : "r"(u));
    return r;
}

#define FMA2(d, a, b) asm("fma.rn.f32x2 %0, %1, %2, %0;" : "+l"(d) : "l"(a), "l"(b))

union F2U { unsigned long long u; float2 f; };

// ---------------------------------------------------------------------------
__global__ void vq_init() {
    g_loss_sum = 0.0;
    g_rare_cnt = 0;
}

// 0.5*||w_c||^2 per code. <<<KCODES, 256>>>
__global__ void vq_csum(const float* __restrict__ w) {
    __shared__ float ws[8];
    int c = blockIdx.x;
    float v = w[(size_t)c * D + threadIdx.x];
    float s = v * v;
    #pragma unroll
    for (int o = 16; o > 0; o >>= 1) s += __shfl_xor_sync(FULLMASK, s, o);
    if ((threadIdx.x & 31) == 0) ws[threadIdx.x >> 5] = s;
    __syncthreads();
    if (threadIdx.x == 0) {
        float t = 0.f;
        #pragma unroll
        for (int i = 0; i < 8; i++) t += ws[i];
        g_csum[c] = 0.5f * t;
    }
}

// Compact non-pid3 rows. <<<N/256, 256>>>
__global__ void vq_compact(const int* __restrict__ x) {
    int i = blockIdx.x * blockDim.x + threadIdx.x;
    int at = x[2 * (size_t)i];
    if (partition_id(at) != 3) {
        int p = atomicAdd(&g_rare_cnt, 1);
        g_rare_idx[p] = i;
    }
}

// ---------------------------------------------------------------------------
// Main kernel: dense GEMM-argmin of all rows vs partition-3 codes (127, pad 128)
// using packed f32x2 FMA. Fused output + loss for pid3 rows.
// Tile: BM=128 rows x 128 codes x BK=16, 256 threads, 8x8 per-thread tile
// stored as 8 rows x 4 code-pairs of f32x2.
__global__ void __launch_bounds__(256, 2) vq_main(
    const int* __restrict__ x, const float* __restrict__ e,
    const float* __restrict__ w, float* __restrict__ out)
{
    __shared__ __align__(16) char sm[34368];
    unsigned long long* As2 = (unsigned long long*)sm;
    float* Bs  = (float*)(sm + 16384);
    float* cs  = (float*)(sm + 24832);
    int*   sbest   = (int*)(sm + 32768);
    int*   ssecond = (int*)(sm + 33280);
    int*   spid    = (int*)(sm + 33792);
    double* wsum   = (double*)(sm + 34304);

    const int tid   = threadIdx.x;
    const int tx    = tid & 15;
    const int ty    = tid >> 4;
    const int rbase = blockIdx.x * BM;

    // per-tile metadata
    if (tid < 128) {
        cs[tid] = (tid < P3_CODES) ? g_csum[P3_BASE + tid] : CUDART_INF_F;
        int at = x[2 * (size_t)(rbase + tid)];
        spid[tid] = partition_id(at);
    }

    // loader mapping
    const int lrow  = tid >> 1;     // 0..127
    const int lhalf = tid & 1;      // which 8-col half of the 16-wide chunk
    const float* eptr = e + (size_t)(rbase + lrow) * D + lhalf * 8;
    const int    wrow = P3_BASE + (lrow < P3_CODES ? lrow : P3_CODES - 1);
    const float* wptr = w + (size_t)wrow * D + lhalf * 8;

    unsigned long long acc[8][4];
    #pragma unroll
    for (int r = 0; r < 8; r++)
        #pragma unroll
        for (int p = 0; p < 4; p++) acc[r][p] = 0ull;

    // prologue loads
    float4 a0 = *(const float4*)(eptr);
    float4 a1 = *(const float4*)(eptr + 4);
    float4 b0 = *(const float4*)(wptr);
    float4 b1 = *(const float4*)(wptr + 4);

    for (int kc = 0; kc < D; kc += BK) {
        __syncthreads();
        const int kb = lhalf * 8;
        // store A (dup'd pairs), transposed
        As2[(kb + 0) * 128 + lrow] = dup_f32(a0.x);
        As2[(kb + 1) * 128 + lrow] = dup_f32(a0.y);
        As2[(kb + 2) * 128 + lrow] = dup_f32(a0.z);
        As2[(kb + 3) * 128 + lrow] = dup_f32(a0.w);
        As2[(kb + 4) * 128 + lrow] = dup_f32(a1.x);
        As2[(kb + 5) * 128 + lrow] = dup_f32(a1.y);
        As2[(kb + 6) * 128 + lrow] = dup_f32(a1.z);
        As2[(kb + 7) * 128 + lrow] = dup_f32(a1.w);
        // store B transposed
        Bs[(kb + 0) * BN_PAD + lrow] = b0.x;
        Bs[(kb + 1) * BN_PAD + lrow] = b0.y;
        Bs[(kb + 2) * BN_PAD + lrow] = b0.z;
        Bs[(kb + 3) * BN_PAD + lrow] = b0.w;
        Bs[(kb + 4) * BN_PAD + lrow] = b1.x;
        Bs[(kb + 5) * BN_PAD + lrow] = b1.y;
        Bs[(kb + 6) * BN_PAD + lrow] = b1.z;
        Bs[(kb + 7) * BN_PAD + lrow] = b1.w;
        __syncthreads();

        // prefetch next chunk (overlaps with compute)
        if (kc + BK < D) {
            a0 = *(const float4*)(eptr + kc + BK);
            a1 = *(const float4*)(eptr + kc + BK + 4);
            b0 = *(const float4*)(wptr + kc + BK);
            b1 = *(const float4*)(wptr + kc + BK + 4);
        }

        #pragma unroll
        for (int k = 0; k < BK; k++) {
            const ulonglong2* ap = (const ulonglong2*)(As2 + k * 128 + ty * 8);
            ulonglong2 av0 = ap[0], av1 = ap[1], av2 = ap[2], av3 = ap[3];
            const ulonglong2* bp = (const ulonglong2*)(Bs + k * BN_PAD + tx * 8);
            ulonglong2 bv0 = bp[0], bv1 = bp[1];
            unsigned long long a[8] = {av0.x, av0.y, av1.x, av1.y,
                                       av2.x, av2.y, av3.x, av3.y};
            unsigned long long b[4] = {bv0.x, bv0.y, bv1.x, bv1.y};
            #pragma unroll
            for (int r = 0; r < 8; r++)
                #pragma unroll
                for (int p = 0; p < 4; p++)
                    FMA2(acc[r][p], a[r], b[p]);
        }
    }

    // per-thread epilogue: top-2 scores per row over its 8 codes
    float v1[8], v2[8];
    int   n1[8], n2[8];
    #pragma unroll
    for (int r = 0; r < 8; r++) {
        v1[r] = CUDART_INF_F; v2[r] = CUDART_INF_F; n1[r] = 0; n2[r] = 0;
        #pragma unroll
        for (int p = 0; p < 4; p++) {
            F2U u; u.u = acc[r][p];
            int n0 = tx * 8 + 2 * p;
            float s0 = cs[n0]     - u.f.x;
            float s1 = cs[n0 + 1] - u.f.y;
            if (s0 < v1[r]) { v2[r] = v1[r]; n2[r] = n1[r]; v1[r] = s0; n1[r] = n0; }
            else if (s0 < v2[r]) { v2[r] = s0; n2[r] = n0; }
            if (s1 < v1[r]) { v2[r] = v1[r]; n2[r] = n1[r]; v1[r] = s1; n1[r] = n0 + 1; }
            else if (s1 < v2[r]) { v2[r] = s1; n2[r] = n0 + 1; }
        }
    }

    __syncthreads();   // done reading As2/Bs/cs; overlay as reduction arrays
    float* rv1 = (float*)sm;
    int*   rn1 = (int*)(sm + 8192);
    float* rv2 = (float*)(sm + 16384);
    int*   rn2 = (int*)(sm + 24576);
    #pragma unroll
    for (int r = 0; r < 8; r++) {
        int row = ty * 8 + r;
        rv1[row * 16 + tx] = v1[r];  rn1[row * 16 + tx] = n1[r];
        rv2[row * 16 + tx] = v2[r];  rn2[row * 16 + tx] = n2[r];
    }
    __syncthreads();

    if (tid < 128) {
        float b1v = CUDART_INF_F, b2v = CUDART_INF_F;
        int   j1 = 0, j2 = 0;
        for (int t = 0; t < 16; t++) {
            float va = rv1[tid * 16 + t]; int na = rn1[tid * 16 + t];
            if (va < b1v) { b2v = b1v; j2 = j1; b1v = va; j1 = na; }
            else if (va < b2v) { b2v = va; j2 = na; }
            float vb = rv2[tid * 16 + t]; int nb = rn2[tid * 16 + t];
            if (vb < b1v) { b2v = b1v; j2 = j1; b1v = vb; j1 = nb; }
            else if (vb < b2v) { b2v = vb; j2 = nb; }
        }
        sbest[tid]   = P3_BASE + j1;
        ssecond[tid] = (b2v - b1v < MARGIN) ? (P3_BASE + j2) : -1;
    }
    __syncthreads();

    // fused output + loss for pid3 rows (fp64 rescore on near-ties)
    const int wid  = tid >> 5;
    const int lane = tid & 31;
    double ls = 0.0;
    for (int rr = wid; rr < BM; rr += 8) {
        if (spid[rr] != 3) continue;
        const int row = rbase + rr;
        const float* er = e + (size_t)row * D;
        int b = sbest[rr];
        int b2 = ssecond[rr];
        if (b2 >= 0) {
            const float* wa = w + (size_t)b * D;
            const float* wb = w + (size_t)b2 * D;
            double da = 0.0, db = 0.0;
            #pragma unroll
            for (int it = 0; it < 2; it++) {
                int col = it * 128 + lane * 4;
                float4 ev = *(const float4*)(er + col);
                float4 qa = *(const float4*)(wa + col);
                float4 qb = *(const float4*)(wb + col);
                double t;
                t = (double)ev.x - qa.x; da += t * t;
                t = (double)ev.y - qa.y; da += t * t;
                t = (double)ev.z - qa.z; da += t * t;
                t = (double)ev.w - qa.w; da += t * t;
                t = (double)ev.x - qb.x; db += t * t;
                t = (double)ev.y - qb.y; db += t * t;
                t = (double)ev.z - qb.z; db += t * t;
                t = (double)ev.w - qb.w; db += t * t;
            }
            #pragma unroll
            for (int o = 16; o > 0; o >>= 1) {
                da += __shfl_xor_sync(FULLMASK, da, o);
                db += __shfl_xor_sync(FULLMASK, db, o);
            }
            if (db < da || (db == da && b2 < b)) b = b2;
        }
        const float* qr = w + (size_t)b * D;
        float* orow = out + (size_t)row * D;
        #pragma unroll
        for (int it = 0; it < 2; it++) {
            int col = it * 128 + lane * 4;
            float4 ev = *(const float4*)(er + col);
            float4 qv = *(const float4*)(qr + col);
            float dx = qv.x - ev.x, dy = qv.y - ev.y;
            float dz = qv.z - ev.z, dw = qv.w - ev.w;
            float4 ov;
            ov.x = ev.x + dx; ov.y = ev.y + dy; ov.z = ev.z + dz; ov.w = ev.w + dw;
            *(float4*)(orow + col) = ov;
            ls += (double)dx * dx + (double)dy * dy +
                  (double)dz * dz + (double)dw * dw;
        }
    }
    #pragma unroll
    for (int o = 16; o > 0; o >>= 1) ls += __shfl_down_sync(FULLMASK, ls, o);
    if (lane == 0) wsum[wid] = ls;
    __syncthreads();
    if (tid == 0) {
        double s = 0.0;
        #pragma unroll
        for (int i = 0; i < 8; i++) s += wsum[i];
        atomicAdd(&g_loss_sum, s);
    }
}

// ---------------------------------------------------------------------------
// Rare rows (pid != 3): one warp per compacted row. Worst-case grid, early exit.
__global__ void __launch_bounds__(1024) vq_rare(
    const int* __restrict__ x, const float* __restrict__ e,
    const float* __restrict__ w, float* __restrict__ out)
{
    __shared__ double wsums[32];
    const int lane = threadIdx.x & 31;
    const int wloc = threadIdx.x >> 5;
    const int wg   = blockIdx.x * 32 + wloc;
    const int cnt  = g_rare_cnt;

    double ls = 0.0;
    if (wg < cnt) {
        const int row = g_rare_idx[wg];
        int at = x[2 * (size_t)row];
        const int pid = partition_id(at);
        const int s  = c_starts[pid];
        const int en = c_ends[pid];
        float ev[8];
        #pragma unroll
        for (int j = 0; j < 8; j++) ev[j] = e[(size_t)row * D + lane + 32 * j];

        float v1 = CUDART_INF_F, v2 = CUDART_INF_F;
        int   i1 = s, i2 = s;
        for (int c = s; c < en; c++) {
            const float* wr = w + (size_t)c * D;
            float d = 0.f;
            #pragma unroll
            for (int j = 0; j < 8; j++) d = fmaf(ev[j], wr[lane + 32 * j], d);
            #pragma unroll
            for (int o = 16; o > 0; o >>= 1) d += __shfl_xor_sync(FULLMASK, d, o);
            float sc = g_csum[c] - d;
            if (sc < v1) { v2 = v1; i2 = i1; v1 = sc; i1 = c; }
            else if (sc < v2) { v2 = sc; i2 = c; }
        }
        int best = i1;
        if (v2 - v1 < MARGIN) {
            const float* wa = w + (size_t)i1 * D;
            const float* wb = w + (size_t)i2 * D;
            double da = 0.0, db = 0.0;
            #pragma unroll
            for (int j = 0; j < 8; j++) {
                int col = lane + 32 * j;
                double t;
                t = (double)ev[j] - wa[col]; da += t * t;
                t = (double)ev[j] - wb[col]; db += t * t;
            }
            #pragma unroll
            for (int o = 16; o > 0; o >>= 1) {
                da += __shfl_xor_sync(FULLMASK, da, o);
                db += __shfl_xor_sync(FULLMASK, db, o);
            }
            if (db < da || (db == da && i2 < i1)) best = i2;
        }
        const float* wq = w + (size_t)best * D;
        #pragma unroll
        for (int j = 0; j < 8; j++) {
            int col = lane + 32 * j;
            float ee = ev[j];
            float q  = wq[col];
            float df = q - ee;
            out[(size_t)row * D + col] = ee + df;
            ls += (double)df * df;
        }
    }
    #pragma unroll
    for (int o = 16; o > 0; o >>= 1) ls += __shfl_down_sync(FULLMASK, ls, o);
    if (lane == 0) wsums[wloc] = ls;
    __syncthreads();
    if (threadIdx.x == 0) {
        double s = 0.0;
        #pragma unroll
        for (int i = 0; i < 32; i++) s += wsums[i];
        if (s != 0.0) atomicAdd(&g_loss_sum, s);
    }
}

// ---------------------------------------------------------------------------
__global__ void vq_finalize(float* out, long long n_out) {
    double mean = g_loss_sum / (double)((long long)N_ROWS * D);
    float cl = (float)mean;
    out[n_out - 3] = cl;          // codebook_loss
    out[n_out - 2] = cl;          // gnn_loss (identical value)
    out[n_out - 1] = cl + 0.25f * cl;  // vq_loss
}

// ---------------------------------------------------------------------------
extern "C" void kernel_launch(void* const* d_in, const int* in_sizes, int n_in,
                              void* d_out, int out_size) {
    const int*   x = (const int*)d_in[0];
    const float* e = (const float*)d_in[1];
    const float* w = (const float*)d_in[2];
    float* out = (float*)d_out;

    vq_init<<<1, 1>>>();
    vq_csum<<<KCODES, 256>>>(w);
    vq_compact<<<N_ROWS / 256, 256>>>(x);
    vq_main<<<N_ROWS / BM, 256>>>(x, e, w, out);
    vq_rare<<<N_ROWS / 32, 1024>>>(x, e, w, out);
    vq_finalize<<<1, 1>>>(out, (long long)out_size);
}

// round 8
// speedup vs baseline: 1.6705x; 1.6705x over previous
#include <cuda_runtime.h>
#include <cstdint>
#include <cfloat>
#include <math_constants.h>

#define FULLMASK 0xFFFFFFFFu

static constexpr int N_ROWS = 262144;
static constexpr int D      = 256;
static constexpr int KCODES = 640;

static constexpr int BM = 64;            // rows per CTA tile
static constexpr int BK = 16;            // k-chunk
static constexpr int AS = 20;            // smem row stride in floats (16 + 4 pad)
static constexpr int P3_BASE  = 385;
static constexpr int P3_CODES = 127;     // col 127 = dup pad, masked via cs=INF

#define MARGIN_RARE 1e-2f
#define MARGIN_TF32 0.5f

__constant__ int c_starts[6] = {0, 129, 257, 385, 513, 577};
__constant__ int c_ends[6]   = {128, 256, 384, 512, 576, 640};

__device__ double g_loss_sum;
__device__ int    g_rare_cnt;
__device__ int    g_rare_idx[N_ROWS];
__device__ float  g_csum[KCODES];        // 0.5 * ||w_k||^2

// x is int32 on device (JAX x64-disabled downcasts the reference's int64).
__device__ __forceinline__ int partition_id(int at) {
    if (at == 5)   return 0;
    if (at == 6)   return 1;
    if (at == 7)   return 2;
    if (at == 119) return 4;
    if (at == 120) return 5;
    return 3;
}

__device__ __forceinline__ uint32_t smem_u32(const void* p) {
    uint32_t a;
    asm("{ .reg .u64 t; cvta.to.shared.u64 t, %1; cvt.u32.u64 %0, t; }"
        : "=r"(a) : "l"(p));
    return a;
}

__device__ __forceinline__ void cp16(uint32_t dst, const void* src) {
    asm volatile("cp.async.cg.shared.global [%0], [%1], 16;"
                 :: "r"(dst), "l"(src) : "memory");
}
#define CP_COMMIT() asm volatile("cp.async.commit_group;" ::: "memory")
#define CP_WAIT(n)  asm volatile("cp.async.wait_group %0;" :: "n"(n) : "memory")

#define MMA_TF32(d, a, b0, b1) \
    asm volatile("mma.sync.aligned.m16n8k8.row.col.f32.tf32.tf32.f32 " \
        "{%0,%1,%2,%3}, {%4,%5,%6,%7}, {%8,%9}, {%0,%1,%2,%3};" \
        : "+f"(d[0]), "+f"(d[1]), "+f"(d[2]), "+f"(d[3]) \
        : "r"(a[0]), "r"(a[1]), "r"(a[2]), "r"(a[3]), "r"(b0), "r"(b1))

// ---------------------------------------------------------------------------
// smem layout (bytes) — static, < 48KB, no opt-in needed
static constexpr int SM_CS     = 0;                 // 128 f32
static constexpr int SM_SPID   = 512;               // 64 int
static constexpr int SM_CHOSEN = 768;               // 64 int
static constexpr int SM_WL     = 1024;              // 64 int
static constexpr int SM_SV1    = 1280;              // 64 f32
static constexpr int SM_WSUM   = 1536;              // 8 double
static constexpr int SM_WLCNT  = 1600;              // 1 int (pad to 1664)
static constexpr int SM_PT     = 1664;              // pv1/pn1/pv2/pn2: 4 * 256 * 4B
static constexpr int SM_BUF    = SM_PT + 4096;      // 5760, 16B aligned
static constexpr int STAGE_BYTES = (BM + 128) * AS * 4;   // 15360
static constexpr int SCORE_ST  = 131;               // scores stride (floats)
static constexpr int SCORES_BYTES = BM * SCORE_ST * 4;    // 33536 > 2*STAGE_BYTES
static constexpr int SMEM_MAIN = SM_BUF + SCORES_BYTES;   // 39296

// ---------------------------------------------------------------------------
__global__ void vq_init() {
    g_loss_sum = 0.0;
    g_rare_cnt = 0;
}

__global__ void vq_csum(const float* __restrict__ w) {
    __shared__ float ws[8];
    int c = blockIdx.x;
    float v = w[(size_t)c * D + threadIdx.x];
    float s = v * v;
    #pragma unroll
    for (int o = 16; o > 0; o >>= 1) s += __shfl_xor_sync(FULLMASK, s, o);
    if ((threadIdx.x & 31) == 0) ws[threadIdx.x >> 5] = s;
    __syncthreads();
    if (threadIdx.x == 0) {
        float t = 0.f;
        #pragma unroll
        for (int i = 0; i < 8; i++) t += ws[i];
        g_csum[c] = 0.5f * t;
    }
}

__global__ void vq_compact(const int* __restrict__ x) {
    int i = blockIdx.x * blockDim.x + threadIdx.x;
    int at = x[2 * (size_t)i];
    if (partition_id(at) != 3) {
        int p = atomicAdd(&g_rare_cnt, 1);
        g_rare_idx[p] = i;
    }
}

// top-2 merge with index tiebreak
__device__ __forceinline__ void top2_merge(float& v1, int& n1, float& v2, int& n2,
                                           float vo, int no) {
    if (vo < v1 || (vo == v1 && no < n1)) {
        v2 = v1; n2 = n1; v1 = vo; n1 = no;
    } else if (vo < v2 || (vo == v2 && no < n2)) {
        v2 = vo; n2 = no;
    }
}

// ---------------------------------------------------------------------------
// Main: tf32 mma.sync GEMM-argmin of all rows vs partition-3 codes.
// Tile 64x128x16, 8 warps (2 row-warps x 4 col-warps), static smem.
// ---------------------------------------------------------------------------
__global__ void __launch_bounds__(256) vq_main_mma(
    const int* __restrict__ x, const float* __restrict__ e,
    const float* __restrict__ w, float* __restrict__ out)
{
    __shared__ __align__(16) char sm[SMEM_MAIN];
    const uint32_t smb = smem_u32(sm);
    float*  cs      = (float*)(sm + SM_CS);
    int*    spid    = (int*)(sm + SM_SPID);
    int*    schosen = (int*)(sm + SM_CHOSEN);
    int*    wl      = (int*)(sm + SM_WL);
    float*  sv1     = (float*)(sm + SM_SV1);
    double* wsum    = (double*)(sm + SM_WSUM);
    int*    wlcnt   = (int*)(sm + SM_WLCNT);
    float*  pv1     = (float*)(sm + SM_PT);
    int*    pn1     = (int*)(sm + SM_PT + 1024);
    float*  pv2     = (float*)(sm + SM_PT + 2048);
    int*    pn2     = (int*)(sm + SM_PT + 3072);
    float*  scores  = (float*)(sm + SM_BUF);        // overlay after mainloop

    const int tid  = threadIdx.x;
    const int wid  = tid >> 5;
    const int lane = tid & 31;
    const int g    = lane >> 2;
    const int tig  = lane & 3;
    const int wrow = wid & 1;         // 2 row-warps (32 rows each)
    const int wcol = wid >> 1;        // 4 col-warps (32 cols each)
    const int rbase = blockIdx.x * BM;

    if (tid == 0) *wlcnt = 0;
    if (tid < 128)
        cs[tid] = (tid < P3_CODES) ? g_csum[P3_BASE + tid] : CUDART_INF_F;
    if (tid < BM)
        spid[tid] = partition_id(x[2 * (size_t)(rbase + tid)]);

    // ---- stage issue (A: 64 e-rows, B: 128 w-codes, 16 k each) ----
    auto issue = [&](int buf, int kc) {
        uint32_t abase = smb + SM_BUF + buf * STAGE_BYTES;
        uint32_t bbase = abase + BM * AS * 4;
        {   // A: 64 rows * 4 segs = 256 cp16
            int row = tid >> 2, seg = tid & 3;
            cp16(abase + (row * AS + seg * 4) * 4,
                 e + (size_t)(rbase + row) * D + kc * BK + seg * 4);
        }
        #pragma unroll
        for (int t = 0; t < 2; t++) {   // B: 128 rows * 4 segs = 512 cp16
            int id = tid + t * 256;
            int row = id >> 2, seg = id & 3;
            int wr = row < P3_CODES ? row : P3_CODES - 1;
            cp16(bbase + (row * AS + seg * 4) * 4,
                 w + (size_t)(P3_BASE + wr) * D + kc * BK + seg * 4);
        }
    };

    float acc[2][4][4];
    #pragma unroll
    for (int rT = 0; rT < 2; rT++)
        #pragma unroll
        for (int c = 0; c < 4; c++)
            #pragma unroll
            for (int v = 0; v < 4; v++) acc[rT][c][v] = 0.f;

    issue(0, 0);
    CP_COMMIT();

    for (int kc = 0; kc < 16; kc++) {
        if (kc < 15) { issue((kc + 1) & 1, kc + 1); CP_COMMIT(); CP_WAIT(1); }
        else         { CP_WAIT(0); }
        __syncthreads();

        const uint32_t* Abuf = (const uint32_t*)(sm + SM_BUF + (kc & 1) * STAGE_BYTES);
        const uint32_t* Bbuf = Abuf + BM * AS;

        #pragma unroll
        for (int ks = 0; ks < 2; ks++) {
            const int k0 = ks * 8;
            uint32_t a[2][4];
            #pragma unroll
            for (int rT = 0; rT < 2; rT++) {
                int ab = (wrow * 32 + rT * 16 + g) * AS + k0 + tig;
                a[rT][0] = Abuf[ab];
                a[rT][1] = Abuf[ab + 8 * AS];
                a[rT][2] = Abuf[ab + 4];
                a[rT][3] = Abuf[ab + 8 * AS + 4];
            }
            #pragma unroll
            for (int c = 0; c < 4; c++) {
                int nb = (wcol * 32 + c * 8 + g) * AS + k0 + tig;
                uint32_t b0 = Bbuf[nb], b1 = Bbuf[nb + 4];
                MMA_TF32(acc[0][c], a[0], b0, b1);
                MMA_TF32(acc[1][c], a[1], b0, b1);
            }
        }
        __syncthreads();
    }

    // ---- scores -> smem overlay; per-thread top-2, in-warp tig reduce ----
    #pragma unroll
    for (int rT = 0; rT < 2; rT++) {
        #pragma unroll
        for (int hv = 0; hv < 2; hv++) {
            const int row = wrow * 32 + rT * 16 + hv * 8 + g;
            float v1 = CUDART_INF_F, v2 = CUDART_INF_F;
            int n1 = 0x7FFFFFFF, n2 = 0x7FFFFFFF;
            #pragma unroll
            for (int c = 0; c < 4; c++) {
                #pragma unroll
                for (int p = 0; p < 2; p++) {
                    const int col = wcol * 32 + c * 8 + 2 * tig + p;
                    float sc = cs[col] - acc[rT][c][hv * 2 + p];
                    scores[row * SCORE_ST + col] = sc;
                    top2_merge(v1, n1, v2, n2, sc, col);
                }
            }
            // reduce across the 4 tig lanes holding the same row
            #pragma unroll
            for (int o = 1; o <= 2; o <<= 1) {
                float ov1 = __shfl_xor_sync(FULLMASK, v1, o);
                int   on1 = __shfl_xor_sync(FULLMASK, n1, o);
                float ov2 = __shfl_xor_sync(FULLMASK, v2, o);
                int   on2 = __shfl_xor_sync(FULLMASK, n2, o);
                top2_merge(v1, n1, v2, n2, ov1, on1);
                top2_merge(v1, n1, v2, n2, ov2, on2);
            }
            if (tig == 0) {
                pv1[row * 4 + wcol] = v1;  pn1[row * 4 + wcol] = n1;
                pv2[row * 4 + wcol] = v2;  pn2[row * 4 + wcol] = n2;
            }
        }
    }
    __syncthreads();

    // ---- per-row reduce over 4 col-warp slots ----
    if (tid < BM) {
        float v1 = CUDART_INF_F, v2 = CUDART_INF_F;
        int n1 = 0x7FFFFFFF, n2 = 0x7FFFFFFF;
        #pragma unroll
        for (int s = 0; s < 4; s++) {
            top2_merge(v1, n1, v2, n2, pv1[tid * 4 + s], pn1[tid * 4 + s]);
            top2_merge(v1, n1, v2, n2, pv2[tid * 4 + s], pn2[tid * 4 + s]);
        }
        schosen[tid] = P3_BASE + n1;
        sv1[tid] = v1;
        if (v2 - v1 < MARGIN_TF32) {
            int p = atomicAdd(wlcnt, 1);
            wl[p] = tid;
        }
    }
    __syncthreads();

    // ---- exact fp64 rescore of flagged rows (warp per row) ----
    {
        const int nwl = *wlcnt;
        for (int k = wid; k < nwl; k += 8) {
            const int row = wl[k];
            const float thr = sv1[row] + MARGIN_TF32;
            const float* er = e + (size_t)(rbase + row) * D;
            float ev[8];
            #pragma unroll
            for (int j = 0; j < 8; j++) ev[j] = er[lane + 32 * j];
            double bestd = DBL_MAX;
            int    bestc = 0x7FFFFFFF;
            #pragma unroll
            for (int base = 0; base < 128; base += 32) {
                int c = base + lane;
                bool ok = (c < P3_CODES) && (scores[row * SCORE_ST + c] < thr);
                unsigned m = __ballot_sync(FULLMASK, ok);
                while (m) {
                    int c2 = base + __ffs(m) - 1;
                    m &= m - 1;
                    const float* wr = w + (size_t)(P3_BASE + c2) * D;
                    double s = 0.0;
                    #pragma unroll
                    for (int j = 0; j < 8; j++) {
                        double t = (double)ev[j] - (double)wr[lane + 32 * j];
                        s += t * t;
                    }
                    #pragma unroll
                    for (int o = 16; o > 0; o >>= 1)
                        s += __shfl_xor_sync(FULLMASK, s, o);
                    if (s < bestd) { bestd = s; bestc = c2; }   // ascending c2 → ties keep lowest
                }
            }
            if (lane == 0) schosen[row] = P3_BASE + bestc;
        }
    }
    __syncthreads();

    // ---- output + loss for pid3 rows (warp per 8 rows) ----
    double ls = 0.0;
    #pragma unroll
    for (int j = 0; j < 8; j++) {
        const int row = wid * 8 + j;
        if (spid[row] != 3) continue;
        const float* er = e + (size_t)(rbase + row) * D;
        const float* wr = w + (size_t)schosen[row] * D;
        float* orow = out + (size_t)(rbase + row) * D;
        #pragma unroll
        for (int it = 0; it < 2; it++) {
            int f4 = it * 32 + lane;
            float4 ev = *(const float4*)(er + f4 * 4);
            float4 qv = *(const float4*)(wr + f4 * 4);
            float dx = qv.x - ev.x, dy = qv.y - ev.y;
            float dz = qv.z - ev.z, dw = qv.w - ev.w;
            float4 ov;
            ov.x = ev.x + dx; ov.y = ev.y + dy; ov.z = ev.z + dz; ov.w = ev.w + dw;
            *(float4*)(orow + f4 * 4) = ov;
            ls += (double)dx * dx + (double)dy * dy +
                  (double)dz * dz + (double)dw * dw;
        }
    }
    #pragma unroll
    for (int o = 16; o > 0; o >>= 1) ls += __shfl_down_sync(FULLMASK, ls, o);
    if (lane == 0) wsum[wid] = ls;
    __syncthreads();
    if (tid == 0) {
        double s = 0.0;
        #pragma unroll
        for (int i = 0; i < 8; i++) s += wsum[i];
        atomicAdd(&g_loss_sum, s);
    }
}

// ---------------------------------------------------------------------------
// Rare rows: grid-stride, one warp per compacted row.
__global__ void __launch_bounds__(1024) vq_rare(
    const int* __restrict__ x, const float* __restrict__ e,
    const float* __restrict__ w, float* __restrict__ out)
{
    __shared__ double wsums[32];
    const int lane = threadIdx.x & 31;
    const int wloc = threadIdx.x >> 5;
    const int cnt  = g_rare_cnt;

    double ls = 0.0;
    for (int wg = blockIdx.x * 32 + wloc; wg < cnt; wg += gridDim.x * 32) {
        const int row = g_rare_idx[wg];
        int at = x[2 * (size_t)row];
        const int pid = partition_id(at);
        const int s  = c_starts[pid];
        const int en = c_ends[pid];
        float ev[8];
        #pragma unroll
        for (int j = 0; j < 8; j++) ev[j] = e[(size_t)row * D + lane + 32 * j];

        float v1 = CUDART_INF_F, v2 = CUDART_INF_F;
        int   i1 = s, i2 = s;
        for (int c = s; c < en; c++) {
            const float* wr = w + (size_t)c * D;
            float d = 0.f;
            #pragma unroll
            for (int j = 0; j < 8; j++) d = fmaf(ev[j], wr[lane + 32 * j], d);
            #pragma unroll
            for (int o = 16; o > 0; o >>= 1) d += __shfl_xor_sync(FULLMASK, d, o);
            float sc = g_csum[c] - d;
            if (sc < v1) { v2 = v1; i2 = i1; v1 = sc; i1 = c; }
            else if (sc < v2) { v2 = sc; i2 = c; }
        }
        int best = i1;
        if (v2 - v1 < MARGIN_RARE) {
            const float* wa = w + (size_t)i1 * D;
            const float* wb = w + (size_t)i2 * D;
            double da = 0.0, db = 0.0;
            #pragma unroll
            for (int j = 0; j < 8; j++) {
                int col = lane + 32 * j;
                double t;
                t = (double)ev[j] - wa[col]; da += t * t;
                t = (double)ev[j] - wb[col]; db += t * t;
            }
            #pragma unroll
            for (int o = 16; o > 0; o >>= 1) {
                da += __shfl_xor_sync(FULLMASK, da, o);
                db += __shfl_xor_sync(FULLMASK, db, o);
            }
            if (db < da || (db == da && i2 < i1)) best = i2;
        }
        const float* wq = w + (size_t)best * D;
        #pragma unroll
        for (int j = 0; j < 8; j++) {
            int col = lane + 32 * j;
            float ee = ev[j];
            float q  = wq[col];
            float df = q - ee;
            out[(size_t)row * D + col] = ee + df;
            ls += (double)df * df;
        }
    }
    #pragma unroll
    for (int o = 16; o > 0; o >>= 1) ls += __shfl_down_sync(FULLMASK, ls, o);
    if (lane == 0) wsums[wloc] = ls;
    __syncthreads();
    if (threadIdx.x == 0) {
        double s = 0.0;
        #pragma unroll
        for (int i = 0; i < 32; i++) s += wsums[i];
        if (s != 0.0) atomicAdd(&g_loss_sum, s);
    }
}

// ---------------------------------------------------------------------------
__global__ void vq_finalize(float* out, long long n_out) {
    double mean = g_loss_sum / (double)((long long)N_ROWS * D);
    float cl = (float)mean;
    out[n_out - 3] = cl;               // codebook_loss
    out[n_out - 2] = cl;               // gnn_loss (identical value)
    out[n_out - 1] = cl + 0.25f * cl;  // vq_loss
}

// ---------------------------------------------------------------------------
extern "C" void kernel_launch(void* const* d_in, const int* in_sizes, int n_in,
                              void* d_out, int out_size) {
    const int*   x = (const int*)d_in[0];
    const float* e = (const float*)d_in[1];
    const float* w = (const float*)d_in[2];
    float* out = (float*)d_out;

    vq_init<<<1, 1>>>();
    vq_csum<<<KCODES, 256>>>(w);
    vq_compact<<<N_ROWS / 256, 256>>>(x);
    vq_main_mma<<<N_ROWS / BM, 256>>>(x, e, w, out);
    vq_rare<<<256, 1024>>>(x, e, w, out);
    vq_finalize<<<1, 1>>>(out, (long long)out_size);
}